// round 15
// baseline (speedup 1.0000x reference)
#include <cuda_runtime.h>
#include <math.h>
#include <stdint.h>
#include <stddef.h>

typedef unsigned long long ull;

// Problem dims
static constexpr int S_LEN = 512;
static constexpr int BATCH = 64;
static constexpr int IDIM  = 256;
static constexpr int HDIM  = 512;
static constexpr int EDIM  = 512;

// Grid: 128 worker CTAs (64 clusters x 2 k-split ranks) + leader CTA (+1 idle)
static constexpr int GW  = 128;
static constexpr int G   = 130;
static constexpr int NT  = 512;   // warps 0-7: h-chain, warps 8-15: a-chain

// smem byte offsets
static constexpr int OFF_WHD   = 0;        // 256k x 8c ull dup  = 16384
static constexpr int OFF_WAD   = 16384;    // 512k x 8c ull dup  = 32768
static constexpr int OFF_REDH  = 49152;    // 8w x 8c x 32bp ull = 16384
static constexpr int OFF_REDA  = 65536;    // 16384
static constexpr int OFF_MBOXH = 81920;    // 2src x 4c x 32bp ull = 2048
static constexpr int OFF_MBOXA = 83968;    // 2048
static constexpr int OFF_MBFH  = 86016;    // 2 ints
static constexpr int OFF_MBFA  = 86024;    // 2 ints
static constexpr int SMEM_BYTES = 86048;

// Device scratch (allocation-free rule)
__device__ float g_xw[(size_t)S_LEN * HDIM * BATCH];  // [t][c][b]
__device__ float g_h[2][HDIM * BATCH];                // [c][b] parity buffers
__device__ float g_a[2][EDIM * BATCH];
__device__ int   g_arr[GW];   // worker arrive flags (equality, leader-paced)
__device__ int   g_rel;       // leader release word

// ---------------- f32x2 helpers ----------------
__device__ __forceinline__ ull packdup(float w) {
    ull r; unsigned u = __float_as_uint(w);
    asm("mov.b64 %0, {%1, %2};" : "=l"(r) : "r"(u), "r"(u));
    return r;
}
__device__ __forceinline__ ull pack2f(float a, float b) {
    ull r; asm("mov.b64 %0, {%1, %2};" : "=l"(r) : "f"(a), "f"(b));
    return r;
}
__device__ __forceinline__ float2 unpk(ull v) {
    float2 r; asm("mov.b64 {%0, %1}, %2;" : "=f"(r.x), "=f"(r.y) : "l"(v));
    return r;
}
__device__ __forceinline__ ull fma2(ull a, ull b, ull c) {
    ull d; asm("fma.rn.f32x2 %0, %1, %2, %3;" : "=l"(d) : "l"(a), "l"(b), "l"(c));
    return d;
}
__device__ __forceinline__ ull add2(ull a, ull b) {
    ull d; asm("add.rn.f32x2 %0, %1, %2;" : "=l"(d) : "l"(a), "l"(b));
    return d;
}

// ---------------- sync / DSMEM helpers ----------------
__device__ __forceinline__ unsigned s2u(const void* p) {
    unsigned a;
    asm("{ .reg .u64 t; cvta.to.shared.u64 t, %1; cvt.u32.u64 %0, t; }"
        : "=r"(a) : "l"(p));
    return a;
}
__device__ __forceinline__ void dsmem_st64(unsigned laddr, int rk, ull v) {
    unsigned ra;
    asm volatile("mapa.shared::cluster.u32 %0, %1, %2;" : "=r"(ra) : "r"(laddr), "r"(rk));
    asm volatile("st.shared::cluster.b64 [%0], %1;" :: "r"(ra), "l"(v) : "memory");
}
__device__ __forceinline__ void dsmem_st32(unsigned laddr, int rk, int v) {
    unsigned ra;
    asm volatile("mapa.shared::cluster.u32 %0, %1, %2;" : "=r"(ra) : "r"(laddr), "r"(rk));
    asm volatile("st.shared::cluster.b32 [%0], %1;" :: "r"(ra), "r"(v) : "memory");
}
__device__ __forceinline__ void fence_cluster() {
    asm volatile("fence.acq_rel.cluster;" ::: "memory");
}
__device__ __forceinline__ void barn(int id) {   // named barrier, 256 threads
    asm volatile("bar.sync %0, 256;" :: "r"(id) : "memory");
}

// Leader-paced equality barrier (proven; replay-safe: values strictly 1..S+1)
__device__ __forceinline__ void worker_barrier(int bid, int v) {
    __syncthreads();
    if (threadIdx.x == 0) {
        __threadfence();
        *(volatile int*)&g_arr[bid] = v;
        while (*(volatile int*)&g_rel != v) { }
        __threadfence();
    }
    __syncthreads();
}

// ---------------------------------------------------------------------------
// Precompute GEMM: g_xw[t][j][b] = sum_i x[b][t][i]*W_ih[j][i] + b_ih[j]+b_hh[j]
// ---------------------------------------------------------------------------
__global__ __launch_bounds__(256) void xw_gemm(const float* __restrict__ x,
                                               const float* __restrict__ W_ih,
                                               const float* __restrict__ b_ih,
                                               const float* __restrict__ b_hh) {
    __shared__ float As[16][68];
    __shared__ float Bs[16][68];

    const int r0 = blockIdx.x * 64;
    const int j0 = blockIdx.y * 64;
    const int tx = threadIdx.x & 15;
    const int ty = threadIdx.x >> 4;

    float acc[4][4] = {};

    for (int k0 = 0; k0 < IDIM; k0 += 16) {
#pragma unroll
        for (int m = 0; m < 4; ++m) {
            int lin = threadIdx.x + 256 * m;
            int rr = lin >> 4, kk = lin & 15;
            As[kk][rr] = x[(size_t)(r0 + rr) * IDIM + k0 + kk];
            Bs[kk][rr] = W_ih[(size_t)(j0 + rr) * IDIM + k0 + kk];
        }
        __syncthreads();
#pragma unroll
        for (int kk = 0; kk < 16; ++kk) {
            float4 av = *(const float4*)&As[kk][ty * 4];
            float4 bv = *(const float4*)&Bs[kk][tx * 4];
            float af[4] = {av.x, av.y, av.z, av.w};
            float bf[4] = {bv.x, bv.y, bv.z, bv.w};
#pragma unroll
            for (int i = 0; i < 4; ++i)
#pragma unroll
                for (int j = 0; j < 4; ++j)
                    acc[i][j] += af[i] * bf[j];
        }
        __syncthreads();
    }

#pragma unroll
    for (int i = 0; i < 4; ++i) {
        int r = r0 + ty * 4 + i;
        int t = r & (S_LEN - 1);
        int b = r >> 9;
#pragma unroll
        for (int j = 0; j < 4; ++j) {
            int col = j0 + tx * 4 + j;
            g_xw[((size_t)t * HDIM + col) * BATCH + b] = acc[i][j] + b_ih[col] + b_hh[col];
        }
    }
}

// ---------------------------------------------------------------------------
// Persistent RNN kernel: 64 clusters x 2 ranks; per-chain pipelined tails.
// Round r (0..S): h_{r+1} = tanh(xw_r + h_r W_hh^T)               [r < S]
//                 a_r     = tanh(h_r W_ya^T + a_{r-1} W_aa^T + b) [a_0 = 0; r==S -> out]
// Rank 0 computes the h_r·W_ya half of a; rank 1 the a_{r-1}·W_aa half.
// ---------------------------------------------------------------------------
__global__ __launch_bounds__(NT, 1) __cluster_dims__(2, 1, 1)
void rnn_all(const float* __restrict__ W_hh,
             const float* __restrict__ W_ya,
             const float* __restrict__ b_ya,
             const float* __restrict__ W_aa,
             const float* __restrict__ b_aa,
             float* __restrict__ out) {
    extern __shared__ char smem[];
    ull* wHd   = (ull*)(smem + OFF_WHD);
    ull* wAd   = (ull*)(smem + OFF_WAD);
    ull* redH  = (ull*)(smem + OFF_REDH);
    ull* redA  = (ull*)(smem + OFF_REDA);
    ull* mboxH = (ull*)(smem + OFF_MBOXH);
    ull* mboxA = (ull*)(smem + OFF_MBOXA);
    volatile int* mbfH = (volatile int*)(smem + OFF_MBFH);
    volatile int* mbfA = (volatile int*)(smem + OFF_MBFA);

    const int tid = threadIdx.x;
    const int bid = blockIdx.x;

    // ---- leader CTA paces the grid barrier ----
    if (bid >= GW) {
        if (bid == GW) {
            for (int v = 1; v <= S_LEN + 1; ++v) {
                if (tid < GW) { while (*(volatile int*)&g_arr[tid] != v) { } }
                __syncthreads();
                if (tid == 0) { __threadfence(); *(volatile int*)&g_rel = v; }
                __syncthreads();
            }
        }
        return;
    }

    const int cl = bid >> 1;         // cluster 0..63
    const int ks = bid & 1;          // rank in cluster
    const int c0 = cl * 8;           // 8 columns per cluster

    const unsigned mboxH_u = s2u((const void*)mboxH);
    const unsigned mboxA_u = s2u((const void*)mboxA);
    const unsigned mbfH_u  = s2u((const void*)mbfH);
    const unsigned mbfA_u  = s2u((const void*)mbfA);

    // ---- init: zero state, load weights, reset mbf ----
    for (int i = bid * NT + tid; i < HDIM * BATCH / 2; i += GW * NT) {
        ((ull*)g_h[0])[i] = 0ull;   // h_0 = 0
        ((ull*)g_a[1])[i] = 0ull;   // a_{-1} slot (finite, never used numerically)
    }
    // wHd[k][c]: rank's 256-k slice of W_hh for cluster cols
    for (int i = tid; i < 256 * 8; i += NT) {
        int k = i >> 3, c = i & 7;
        wHd[i] = packdup(__ldg(&W_hh[(size_t)(c0 + c) * HDIM + ks * 256 + k]));
    }
    // wAd[k][c]: rank 0 -> W_ya (K=512), rank 1 -> W_aa (K=512)
    for (int i = tid; i < 512 * 8; i += NT) {
        int k = i >> 3, c = i & 7;
        float v = (ks == 0) ? __ldg(&W_ya[(size_t)(c0 + c) * HDIM + k])
                            : __ldg(&W_aa[(size_t)(c0 + c) * EDIM + k]);
        wAd[i] = packdup(v);
    }
    if (tid < 2) { mbfH[tid] = 0; mbfA[tid] = 0; }

    // prefetch xw for round 0
    const int jX  = (tid >> 5) & 3;          // used by h-combine threads (tid<128)
    const int bpX = tid & 31;
    const int cX  = c0 + ks * 4 + jX;
    ull xwv = 0ull;
    if (tid < 128)
        xwv = __ldcg((const ull*)(g_xw + ((size_t)0 * HDIM + cX) * BATCH) + bpX);

    worker_barrier(bid, 1);

    for (int r = 0; r <= S_LEN; ++r) {
        const int p = r & 1;

        if (tid < 256) {
            // ================= h-chain (warps 0-7) =================
            const int w  = tid >> 5;        // 0..7
            const int bp = tid & 31;

            // h-GEMM: warp w covers 32-k slice of rank's 256-k range, 8 cols
            ull acc[8];
#pragma unroll
            for (int c = 0; c < 8; ++c) acc[c] = 0ull;
            {
                const ull* hsrc = (const ull*)(g_h[p] + (ks * 256 + w * 32) * BATCH) + bp;
                const ull* whr  = wHd + (w * 32) * 8;
#pragma unroll
                for (int kk = 0; kk < 32; ++kk) {
                    ull hv = __ldcg(hsrc + kk * 32);
                    const ulonglong2* wp = (const ulonglong2*)(whr + kk * 8);
#pragma unroll
                    for (int cp = 0; cp < 4; ++cp) {
                        ulonglong2 w2 = wp[cp];
                        acc[2 * cp]     = fma2(hv, w2.x, acc[2 * cp]);
                        acc[2 * cp + 1] = fma2(hv, w2.y, acc[2 * cp + 1]);
                    }
                }
            }
#pragma unroll
            for (int c = 0; c < 8; ++c) redH[(w * 8 + c) * 32 + bp] = acc[c];
            barn(1);

            // reduce (1 output/thread) + DSMEM scatter to column owner
            {
                const int cc = tid >> 5;     // 0..7
                ull s = redH[cc * 32 + bp];
#pragma unroll
                for (int ww = 1; ww < 8; ++ww)
                    s = add2(s, redH[(ww * 8 + cc) * 32 + bp]);
                dsmem_st64(mboxH_u + (((ks * 4 + (cc & 3)) * 32 + bp) << 3), cc >> 2, s);
            }
            fence_cluster();
            barn(1);
            if (tid == 0) {
                dsmem_st32(mbfH_u + ks * 4, 0, r + 2);
                dsmem_st32(mbfH_u + ks * 4, 1, r + 2);
            }
            if (tid < 2) { while (mbfH[tid] != r + 2) { } }
            fence_cluster();
            barn(1);

            // h-combine: 2-way add + xw + tanh -> publish h_{r+1}
            if (tid < 128 && r < S_LEN) {
                ull v = add2(mboxH[(0 * 4 + jX) * 32 + bpX],
                             mboxH[(1 * 4 + jX) * 32 + bpX]);
                v = add2(v, xwv);
                float2 f = unpk(v);
                f.x = tanhf(f.x); f.y = tanhf(f.y);
                *(ull*)(g_h[p ^ 1] + cX * BATCH + 2 * bpX) = pack2f(f.x, f.y);
            }
            // prefetch next round's xw under the coming barrier
            if (tid < 128 && r + 1 < S_LEN)
                xwv = __ldcg((const ull*)(g_xw + ((size_t)(r + 1) * HDIM + cX) * BATCH) + bpX);
        } else {
            // ================= a-chain (warps 8-15) =================
            const int gt = tid - 256;
            const int aw = gt >> 5;         // 0..7
            const int bp = gt & 31;

            // a-GEMM: rank 0 -> h_r slice, rank 1 -> a_{r-1} slice (64 k per warp)
            ull acc[8];
#pragma unroll
            for (int c = 0; c < 8; ++c) acc[c] = 0ull;
            {
                const float* sA = (ks == 0) ? (g_h[p] + (aw * 64) * BATCH)
                                            : (g_a[p ^ 1] + (aw * 64) * BATCH);
                const ull* asrc = (const ull*)sA + bp;
                const ull* war  = wAd + (aw * 64) * 8;
#pragma unroll
                for (int kk = 0; kk < 64; ++kk) {
                    ull hv = __ldcg(asrc + kk * 32);
                    const ulonglong2* wp = (const ulonglong2*)(war + kk * 8);
#pragma unroll
                    for (int cp = 0; cp < 4; ++cp) {
                        ulonglong2 w2 = wp[cp];
                        acc[2 * cp]     = fma2(hv, w2.x, acc[2 * cp]);
                        acc[2 * cp + 1] = fma2(hv, w2.y, acc[2 * cp + 1]);
                    }
                }
            }
#pragma unroll
            for (int c = 0; c < 8; ++c) redA[(aw * 8 + c) * 32 + bp] = acc[c];
            barn(2);

            // reduce + scatter
            {
                const int cc = gt >> 5;
                ull s = redA[cc * 32 + bp];
#pragma unroll
                for (int ww = 1; ww < 8; ++ww)
                    s = add2(s, redA[(ww * 8 + cc) * 32 + bp]);
                dsmem_st64(mboxA_u + (((ks * 4 + (cc & 3)) * 32 + bp) << 3), cc >> 2, s);
            }
            fence_cluster();
            barn(2);
            if (gt == 0) {
                dsmem_st32(mbfA_u + ks * 4, 0, r + 2);
                dsmem_st32(mbfA_u + ks * 4, 1, r + 2);
            }
            if (gt < 2) { while (mbfA[gt] != r + 2) { } }
            fence_cluster();
            barn(2);

            // a-combine: 2-way add + bias + tanh -> publish a_r
            if (gt < 128) {
                const int jC  = (gt >> 5) & 3;
                const int bpC = gt & 31;
                const int cC  = c0 + ks * 4 + jC;
                float2 f;
                if (r == 0) {
                    f.x = 0.f; f.y = 0.f;              // a_0 = 0 exactly
                } else {
                    ull v = add2(mboxA[(0 * 4 + jC) * 32 + bpC],
                                 mboxA[(1 * 4 + jC) * 32 + bpC]);
                    f = unpk(v);
                    float biasC = b_ya[cC] + b_aa[cC];
                    f.x = tanhf(f.x + biasC); f.y = tanhf(f.y + biasC);
                }
                *(ull*)(g_a[p] + cC * BATCH + 2 * bpC) = pack2f(f.x, f.y);
                if (r == S_LEN) {
                    out[(size_t)(2 * bpC) * EDIM + cC]     = f.x;
                    out[(size_t)(2 * bpC + 1) * EDIM + cC] = f.y;
                }
            }
        }

        if (r < S_LEN) worker_barrier(bid, r + 2);
    }

    // clean exit: no CTA leaves while its cluster peer may still scatter to it
    __syncthreads();
    asm volatile("barrier.cluster.arrive.aligned;" ::: "memory");
    asm volatile("barrier.cluster.wait.aligned;" ::: "memory");
}

// ---------------------------------------------------------------------------
extern "C" void kernel_launch(void* const* d_in, const int* in_sizes, int n_in,
                              void* d_out, int out_size) {
    const float* x    = (const float*)d_in[0];
    const float* W_ih = (const float*)d_in[1];
    const float* W_hh = (const float*)d_in[2];
    const float* b_ih = (const float*)d_in[3];
    const float* b_hh = (const float*)d_in[4];
    const float* W_ya = (const float*)d_in[5];
    const float* b_ya = (const float*)d_in[6];
    const float* W_aa = (const float*)d_in[7];
    const float* b_aa = (const float*)d_in[8];
    float* out = (float*)d_out;

    cudaFuncSetAttribute(rnn_all,
                         cudaFuncAttributeMaxDynamicSharedMemorySize, SMEM_BYTES);

    xw_gemm<<<dim3((BATCH * S_LEN) / 64, HDIM / 64), 256>>>(x, W_ih, b_ih, b_hh);
    rnn_all<<<G, NT, SMEM_BYTES>>>(W_hh, W_ya, b_ya, W_aa, b_aa, out);
}